// round 1
// baseline (speedup 1.0000x reference)
#include <cuda_runtime.h>

// GPT2Editor: the reference's softmax is over a size-1 axis -> weights == 1.
// out[s, :] = sum_f ( (h_last @ Wc[f][:, E:2E] + bc[f][E:]) @ Wp[f] + bp[f] )
// broadcast over all s. Dead inputs: encoder_hidden_states, Wq, bq.
//
// E = 2048, F = 4, S_out = 4096.

#define EDIM 2048
#define FDIM 4
#define SOUT 4096

// Scratch (no device allocations allowed).
__device__ float g_v[FDIM * EDIM];  // v rows, one per f
__device__ float g_r[EDIM];         // final broadcast row

// v[f*E+j] = bc[f, E+j];  r[o] = sum_f bp[f, o]
__global__ void init_kernel(const float* __restrict__ bc,
                            const float* __restrict__ bp) {
    int i = blockIdx.x * blockDim.x + threadIdx.x;
    if (i < FDIM * EDIM) {
        int f = i >> 11;          // / 2048
        int j = i & (EDIM - 1);   // % 2048
        g_v[i] = bc[f * 2 * EDIM + EDIM + j];
    }
    if (i < EDIM) {
        float s = 0.0f;
#pragma unroll
        for (int f = 0; f < FDIM; f++) s += bp[f * EDIM + i];
        g_r[i] = s;
    }
}

// v[f, j] += sum_{e in chunk} h_last[e] * Wc[f, e, E + j]
// grid: (E/256 j-tiles, 16 e-chunks, F), block: 256
__global__ void gemv_v_kernel(const float* __restrict__ h_last,
                              const float* __restrict__ Wc) {
    __shared__ float sh[128];
    const int f  = blockIdx.z;
    const int j  = blockIdx.x * 256 + threadIdx.x;
    const int e0 = blockIdx.y * 128;

    if (threadIdx.x < 128) sh[threadIdx.x] = h_last[e0 + threadIdx.x];
    __syncthreads();

    const float* W = Wc + ((size_t)f * EDIM + e0) * (2 * EDIM) + EDIM + j;
    float acc = 0.0f;
#pragma unroll 8
    for (int e = 0; e < 128; e++) {
        acc = fmaf(sh[e], W[(size_t)e * (2 * EDIM)], acc);
    }
    atomicAdd(&g_v[f * EDIM + j], acc);
}

// r[o] += sum_f sum_{e in chunk} v[f, e] * Wp[f, e, o]
// grid: (E/256 o-tiles, 16 e-chunks, F), block: 256
__global__ void gemv_r_kernel(const float* __restrict__ Wp) {
    __shared__ float sv[128];
    const int f  = blockIdx.z;
    const int o  = blockIdx.x * 256 + threadIdx.x;
    const int e0 = blockIdx.y * 128;

    if (threadIdx.x < 128) sv[threadIdx.x] = g_v[f * EDIM + e0 + threadIdx.x];
    __syncthreads();

    const float* W = Wp + ((size_t)f * EDIM + e0) * EDIM + o;
    float acc = 0.0f;
#pragma unroll 8
    for (int e = 0; e < 128; e++) {
        acc = fmaf(sv[e], W[(size_t)e * EDIM], acc);
    }
    atomicAdd(&g_r[o], acc);
}

// out[s, :] = r[:], float4 stores. grid: SOUT blocks of 256 threads,
// each thread writes 2 float4 (row = 2048 floats = 512 float4).
__global__ void bcast_kernel(float4* __restrict__ out) {
    const float4* r4 = reinterpret_cast<const float4*>(g_r);
    const size_t s = blockIdx.x;
    float4 a = r4[threadIdx.x];
    float4 b = r4[threadIdx.x + 256];
    out[s * 512 + threadIdx.x]       = a;
    out[s * 512 + threadIdx.x + 256] = b;
}

extern "C" void kernel_launch(void* const* d_in, const int* in_sizes, int n_in,
                              void* d_out, int out_size) {
    // metadata order: hidden_states, encoder_hidden_states, Wq, bq, Wc, bc, Wp, bp
    const float* hidden = (const float*)d_in[0];
    const float* Wc     = (const float*)d_in[4];
    const float* bc     = (const float*)d_in[5];
    const float* Wp     = (const float*)d_in[6];
    const float* bp     = (const float*)d_in[7];
    float* out = (float*)d_out;

    const float* h_last = hidden + 127 * EDIM;  // hidden_states[0, -1, :]

    init_kernel<<<(FDIM * EDIM + 255) / 256, 256>>>(bc, bp);
    gemv_v_kernel<<<dim3(EDIM / 256, 16, FDIM), 256>>>(h_last, Wc);
    gemv_r_kernel<<<dim3(EDIM / 256, 16, FDIM), 256>>>(Wp);
    bcast_kernel<<<SOUT, 256>>>((float4*)out);
}